// round 15
// baseline (speedup 1.0000x reference)
#include <cuda_runtime.h>
#include <cuda_fp16.h>

#define Bn 8
#define Cn 12
#define Hn 384
#define Wn 384
#define HWc (Hn*Wn)
#define BHWc (Bn*HWc)
#define LAMf 0.05f
#define EPSf 1e-12f
#define INVN (1.0f/147456.0f)
#define SQ3H 0.86602540378443864676f
#define TWO_PI_D 6.283185307179586476925286766559

// ---------------- scratch (static device arrays; allowed) ----------------
__device__ __half2 g_Y[(size_t)Bn*Cn*HWc]; // coil k-space, fp16, 56.6 MB
__device__ __half2 g_M[(size_t)Bn*Cn*HWc]; // maps, fp16, 28.3 MB
__device__ float  g_MSK[(size_t)Bn*Wn*384]; // permuted mask*INVN, 4.7 MB
__device__ float2 g_p[BHWc];
__device__ float2 g_r[BHWc];
__device__ float2 g_Ap[BHWc];
__device__ float  g_rd0[Bn];                // <r0,r0>
__device__ float  g_pApA[16][Bn];           // per-iteration <p,Ap>
__device__ float  g_rApA[16][Bn];           // per-iteration <r,Ap>
__device__ float  g_AApA[16][Bn];           // per-iteration <Ap,Ap>
__device__ float2 g_T[384];                 // W_384^j = (cos, -sin)

struct h2x2 { __half2 a, c; };

// ---------------- complex helpers ----------------
__device__ __forceinline__ float2 cmul(float2 a, float2 b){
    return make_float2(fmaf(a.x,b.x,-a.y*b.y), fmaf(a.x,b.y, a.y*b.x));
}
__device__ __forceinline__ float2 cadd(float2 a, float2 b){ return make_float2(a.x+b.x, a.y+b.y); }
__device__ __forceinline__ float2 csub(float2 a, float2 b){ return make_float2(a.x-b.x, a.y-b.y); }
__device__ __forceinline__ unsigned br5(unsigned x){ return __brev(x) >> 27; }
__device__ __forceinline__ __half2 c2h(float2 v){ return __floats2half2_rn(v.x, v.y); }
__device__ __forceinline__ float2 h2c(__half2 h){ return __half22float2(h); }

// scalar CG chain: after the loop, alpha = alpha_{it-1}, beta = beta_{it-1}
__device__ __forceinline__ void cg_chain(int it, int b, float& alpha, float& beta){
    float rd = g_rd0[b];
    alpha = 0.f; beta = 0.f;
    for (int k = 0; k < it; k++){
        float pap = g_pApA[k][b], rap = g_rApA[k][b], aap = g_AApA[k][b];
        alpha = rd / (pap + EPSf);
        float rdn = fmaf(alpha*alpha, aap, fmaf(-2.f*alpha, rap, rd));
        beta = rdn / (rd + EPSf);
        rd = rdn;
    }
}

// ---------------- FFT-12 in registers, natural in/out, unnormalized -------
template<bool INV>
__device__ __forceinline__ void fft12(float2* v){
    float2 F0[4], F1[4], F2[4];
    {
        float2 x0=v[0], x1=v[3], x2=v[6], x3=v[9];
        float2 t0=cadd(x0,x2), t1=csub(x0,x2), t2=cadd(x1,x3), t3=csub(x1,x3);
        F0[0]=cadd(t0,t2); F0[2]=csub(t0,t2);
        if(!INV){ F0[1]=make_float2(t1.x+t3.y, t1.y-t3.x); F0[3]=make_float2(t1.x-t3.y, t1.y+t3.x); }
        else    { F0[1]=make_float2(t1.x-t3.y, t1.y+t3.x); F0[3]=make_float2(t1.x+t3.y, t1.y-t3.x); }
    }
    {
        float2 x0=v[1], x1=v[4], x2=v[7], x3=v[10];
        float2 t0=cadd(x0,x2), t1=csub(x0,x2), t2=cadd(x1,x3), t3=csub(x1,x3);
        F1[0]=cadd(t0,t2); F1[2]=csub(t0,t2);
        if(!INV){ F1[1]=make_float2(t1.x+t3.y, t1.y-t3.x); F1[3]=make_float2(t1.x-t3.y, t1.y+t3.x); }
        else    { F1[1]=make_float2(t1.x-t3.y, t1.y+t3.x); F1[3]=make_float2(t1.x+t3.y, t1.y-t3.x); }
    }
    {
        float2 x0=v[2], x1=v[5], x2=v[8], x3=v[11];
        float2 t0=cadd(x0,x2), t1=csub(x0,x2), t2=cadd(x1,x3), t3=csub(x1,x3);
        F2[0]=cadd(t0,t2); F2[2]=csub(t0,t2);
        if(!INV){ F2[1]=make_float2(t1.x+t3.y, t1.y-t3.x); F2[3]=make_float2(t1.x-t3.y, t1.y+t3.x); }
        else    { F2[1]=make_float2(t1.x-t3.y, t1.y+t3.x); F2[3]=make_float2(t1.x+t3.y, t1.y-t3.x); }
    }
    const float c1 = SQ3H, s1 = 0.5f;
    const float sg = INV ? -1.f : 1.f;
    F1[1] = cmul(F1[1], make_float2(c1, -sg*s1));
    F2[1] = cmul(F2[1], make_float2(s1, -sg*c1));
    F1[2] = cmul(F1[2], make_float2(s1, -sg*c1));
    F2[2] = cmul(F2[2], make_float2(-s1, -sg*c1));
    F1[3] = INV ? make_float2(-F1[3].y, F1[3].x) : make_float2(F1[3].y, -F1[3].x);
    F2[3] = make_float2(-F2[3].x, -F2[3].y);
    #pragma unroll
    for (int k4 = 0; k4 < 4; k4++){
        float2 a=F0[k4], b=F1[k4], c=F2[k4];
        float2 s=cadd(b,c), d=csub(b,c);
        v[k4] = cadd(a, s);
        float ex = a.x - 0.5f*s.x, ey = a.y - 0.5f*s.y;
        if(!INV){
            v[k4+4] = make_float2(ex + SQ3H*d.y, ey - SQ3H*d.x);
            v[k4+8] = make_float2(ex - SQ3H*d.y, ey + SQ3H*d.x);
        } else {
            v[k4+4] = make_float2(ex - SQ3H*d.y, ey + SQ3H*d.x);
            v[k4+8] = make_float2(ex + SQ3H*d.y, ey - SQ3H*d.x);
        }
    }
}

// ---------------- FFT-32 across lanes ----------------
__device__ __forceinline__ void fft32_fwd(float2* v, const float2* tw, unsigned lane){
    #pragma unroll
    for (int s = 0; s < 5; s++){
        const int h = 16 >> s;
        const bool up = (lane & h) != 0;
        #pragma unroll
        for (int j = 0; j < 12; j++){
            float2 t;
            t.x = __shfl_xor_sync(0xffffffffu, v[j].x, h);
            t.y = __shfl_xor_sync(0xffffffffu, v[j].y, h);
            float2 nv = up ? csub(t, v[j]) : cadd(v[j], t);
            if (s < 4 && up) nv = cmul(nv, tw[s]);
            v[j] = nv;
        }
    }
}
__device__ __forceinline__ void fft32_inv(float2* v, const float2* twc, unsigned lane){
    #pragma unroll
    for (int s = 0; s < 5; s++){
        const int h = 1 << s;
        const bool up = (lane & h) != 0;
        #pragma unroll
        for (int j = 0; j < 12; j++){
            float2 vv = v[j];
            if (s > 0 && up) vv = cmul(vv, twc[4 - s]);
            float2 t;
            t.x = __shfl_xor_sync(0xffffffffu, vv.x, h);
            t.y = __shfl_xor_sync(0xffffffffu, vv.y, h);
            v[j] = up ? csub(t, vv) : cadd(vv, t);
        }
    }
}

__device__ __forceinline__ void load_tw32_fwd(unsigned lane, float2* tw){
    tw[0] = __ldg(&g_T[(lane & 15) * 12]);
    tw[1] = __ldg(&g_T[((lane & 7) * 2) * 12]);
    tw[2] = __ldg(&g_T[((lane & 3) * 4) * 12]);
    tw[3] = __ldg(&g_T[((lane & 1) * 8) * 12]);
}
__device__ __forceinline__ void load_tw32_inv(unsigned lane, float2* tw){
    float2 a;
    a = __ldg(&g_T[(lane & 15) * 12]); tw[0] = make_float2(a.x, -a.y);
    a = __ldg(&g_T[((lane & 7) * 2) * 12]); tw[1] = make_float2(a.x, -a.y);
    a = __ldg(&g_T[((lane & 3) * 4) * 12]); tw[2] = make_float2(a.x, -a.y);
    a = __ldg(&g_T[((lane & 1) * 8) * 12]); tw[3] = make_float2(a.x, -a.y);
}

template<bool CONJ, int NT>
__device__ __forceinline__ void build_t12(float2* T, int tid){
    for (int i = tid; i < 384; i += NT){
        int j = i >> 5, l = i & 31;
        float2 w = __ldg(&g_T[l*j]);
        T[i] = CONJ ? make_float2(w.x, -w.y) : w;
    }
}

// ============================================================================
// K1: warp per (b,row): fwd row FFT of m_c*p for all 12 coils.
// V in REGISTERS (hot: read 12x/coil), occupancy 5 — verified best config.
// UPD: fused CG update — x += a*p; r -= a*Ap; p = r + b*p.
// ============================================================================
template<bool UPD>
__global__ void __launch_bounds__(128,5) k_fwd(float2* __restrict__ x, int it){
    __shared__ float2 Tf[384];
    const unsigned lane = threadIdx.x & 31;
    const int wid = threadIdx.x >> 5;
    const int row = blockIdx.x*4 + wid;
    const int b   = blockIdx.y;

    build_t12<false,128>(Tf, threadIdx.x);
    float2 tw32[4];
    load_tw32_fwd(lane, tw32);

    const int gbase = (b*Hn + row)*Wn;
    float2 V[12];
    if (UPD){
        float alpha, beta;
        cg_chain(it, b, alpha, beta);
        #pragma unroll
        for (int j = 0; j < 12; j++){
            int idx = gbase + (int)lane + 32*j;
            float2 rv = g_r[idx], pv = g_p[idx], ap = g_Ap[idx], xv = x[idx];
            x[idx] = make_float2(fmaf(alpha, pv.x, xv.x), fmaf(alpha, pv.y, xv.y));
            rv = make_float2(fmaf(-alpha, ap.x, rv.x), fmaf(-alpha, ap.y, rv.y));
            g_r[idx] = rv;
            float2 pn = make_float2(fmaf(beta, pv.x, rv.x), fmaf(beta, pv.y, rv.y));
            g_p[idx] = pn;
            V[j] = pn;
        }
    } else {
        #pragma unroll
        for (int j = 0; j < 12; j++) V[j] = g_p[gbase + (int)lane + 32*j];
    }
    __syncthreads();

    for (int c = 0; c < Cn; c++){
        const __half2* mp = g_M + ((size_t)(b*Cn + c)*Hn + row)*Wn;
        float2 X[12];
        #pragma unroll
        for (int j = 0; j < 12; j++) X[j] = cmul(h2c(__ldg(mp + lane + 32*j)), V[j]);
        fft12<false>(X);
        #pragma unroll
        for (int j = 1; j < 12; j++) X[j] = cmul(X[j], Tf[j*32 + lane]);
        fft32_fwd(X, tw32, lane);
        __half2* yo = g_Y + ((size_t)(b*Cn + c)*Hn + row)*Wn;
        #pragma unroll
        for (int j = 0; j < 12; j++) yo[lane + 32*j] = c2h(X[j]);
    }
}

// ============================================================================
// K2: block = 8 columns of one (b,c): col FFT -> mask*INVN -> col IFFT.
// ============================================================================
__global__ void __launch_bounds__(256,3) k_col(){
    __shared__ __half2 S[384*9];
    __shared__ float2 Tf[384], Ti[384];
    const unsigned lane = threadIdx.x & 31;
    const int wcol = threadIdx.x >> 5;
    const int tid = threadIdx.x;
    const int p0 = blockIdx.x*8, c = blockIdx.y, b = blockIdx.z;
    const size_t base = (size_t)(b*Cn + c)*HWc;

    build_t12<false,256>(Tf, tid);
    for (int i = tid; i < 384; i += 256){
        int j = i >> 5, l = i & 31;
        float2 w = __ldg(&g_T[l*j]);
        Ti[i] = make_float2(w.x, -w.y);
    }
    float2 tw32[4], tw32c[4];
    load_tw32_fwd(lane, tw32);
    #pragma unroll
    for (int s = 0; s < 4; s++) tw32c[s] = make_float2(tw32[s].x, -tw32[s].y);

    const int p = p0 + wcol;
    const float* mp2 = g_MSK + ((size_t)(b*Wn + p))*384;
    float msk[12];
    #pragma unroll
    for (int j = 0; j < 12; j++) msk[j] = __ldg(mp2 + lane + 32*j);

    #pragma unroll
    for (int k = 0; k < 3; k++){
        int idx = tid + k*256;
        int h = idx >> 1, c0 = (idx & 1)*4;
        uint4 v = *reinterpret_cast<const uint4*>(g_Y + base + (size_t)h*Wn + p0 + c0);
        unsigned* sp = reinterpret_cast<unsigned*>(S) + h*9 + c0;
        sp[0] = v.x; sp[1] = v.y; sp[2] = v.z; sp[3] = v.w;
    }
    __syncthreads();

    float2 X[12];
    #pragma unroll
    for (int j = 0; j < 12; j++) X[j] = h2c(S[(lane + 32*j)*9 + wcol]);

    fft12<false>(X);
    #pragma unroll
    for (int j = 1; j < 12; j++) X[j] = cmul(X[j], Tf[j*32 + lane]);
    fft32_fwd(X, tw32, lane);

    #pragma unroll
    for (int j = 0; j < 12; j++) X[j] = make_float2(X[j].x*msk[j], X[j].y*msk[j]);

    fft32_inv(X, tw32c, lane);
    #pragma unroll
    for (int j = 1; j < 12; j++) X[j] = cmul(X[j], Ti[j*32 + lane]);
    fft12<true>(X);

    #pragma unroll
    for (int j = 0; j < 12; j++) S[(lane + 32*j)*9 + wcol] = c2h(X[j]);
    __syncthreads();

    #pragma unroll
    for (int k = 0; k < 3; k++){
        int idx = tid + k*256;
        int h = idx >> 1, c0 = (idx & 1)*4;
        const unsigned* sp = reinterpret_cast<const unsigned*>(S) + h*9 + c0;
        uint4 v = make_uint4(sp[0], sp[1], sp[2], sp[3]);
        *reinterpret_cast<uint4*>(g_Y + base + (size_t)h*Wn + p0 + c0) = v;
    }
}

// ============================================================================
// K3: warp per (b,row): inv row FFT per coil, acc (in smem) += conj(m)*z.
// occupancy 6 — verified winner.
// INIT: r = rhs - (acc + lam*p); p = r; reduce <r,r> -> g_rd0.
// else: Ap = acc + lam*p; reduce <p,Ap>, <r,Ap>, <Ap,Ap>.
// ============================================================================
template<bool INIT>
__global__ void __launch_bounds__(128,6) k_inv(int slot){
    __shared__ float2 Ti[384];
    __shared__ float2 Acc[4*384];
    __shared__ float red[4][3];
    const unsigned lane = threadIdx.x & 31;
    const int wid = threadIdx.x >> 5;
    const int row = blockIdx.x*4 + wid;
    const int b   = blockIdx.y;
    const int ab  = wid*384;

    build_t12<true,128>(Ti, threadIdx.x);
    float2 tw32c[4];
    load_tw32_inv(lane, tw32c);
    #pragma unroll
    for (int j = 0; j < 12; j++) Acc[ab + lane + 32*j] = make_float2(0.f, 0.f);
    __syncthreads();

    for (int c = 0; c < Cn; c++){
        const size_t cb = ((size_t)(b*Cn + c)*Hn + row)*Wn;
        float2 X[12];
        #pragma unroll
        for (int j = 0; j < 12; j++) X[j] = h2c(g_Y[cb + lane + 32*j]);
        fft32_inv(X, tw32c, lane);
        #pragma unroll
        for (int j = 1; j < 12; j++) X[j] = cmul(X[j], Ti[j*32 + lane]);
        fft12<true>(X);
        const __half2* mp = g_M + cb;
        #pragma unroll
        for (int j = 0; j < 12; j++){
            float2 m = h2c(__ldg(mp + lane + 32*j));
            float2 z = X[j];
            float2 a0 = Acc[ab + lane + 32*j];
            Acc[ab + lane + 32*j] = make_float2(
                fmaf(m.x, z.x, fmaf(m.y, z.y, a0.x)),
                fmaf(m.x, z.y, fmaf(-m.y, z.x, a0.y)));
        }
    }

    const int gbase = (b*Hn + row)*Wn;
    float s0 = 0.f, s1 = 0.f, s2 = 0.f;
    #pragma unroll
    for (int j = 0; j < 12; j++){
        int idx = gbase + (int)lane + 32*j;
        float2 av = Acc[ab + lane + 32*j];
        float2 pv = g_p[idx];
        float2 o = make_float2(fmaf(LAMf, pv.x, av.x), fmaf(LAMf, pv.y, av.y));
        if (INIT){
            float2 rv = csub(pv, o);        // r = rhs - Aop(rhs)
            g_r[idx] = rv;
            g_p[idx] = rv;                  // p = r
            s0 = fmaf(rv.x, rv.x, fmaf(rv.y, rv.y, s0));
        } else {
            float2 rv = g_r[idx];
            g_Ap[idx] = o;
            s0 = fmaf(pv.x, o.x, fmaf(pv.y, o.y, s0));
            s1 = fmaf(rv.x, o.x, fmaf(rv.y, o.y, s1));
            s2 = fmaf(o.x,  o.x, fmaf(o.y,  o.y, s2));
        }
    }
    #pragma unroll
    for (int off = 16; off > 0; off >>= 1){
        s0 += __shfl_down_sync(0xffffffffu, s0, off);
        if (!INIT){
            s1 += __shfl_down_sync(0xffffffffu, s1, off);
            s2 += __shfl_down_sync(0xffffffffu, s2, off);
        }
    }
    if (lane == 0){ red[wid][0] = s0; red[wid][1] = s1; red[wid][2] = s2; }
    __syncthreads();
    if (threadIdx.x == 0){
        float t0 = red[0][0]+red[1][0]+red[2][0]+red[3][0];
        if (INIT){
            atomicAdd(&g_rd0[b], t0);
        } else {
            float t1 = red[0][1]+red[1][1]+red[2][1]+red[3][1];
            float t2 = red[0][2]+red[1][2]+red[2][2]+red[3][2];
            atomicAdd(&g_pApA[slot][b], t0);
            atomicAdd(&g_rApA[slot][b], t1);
            atomicAdd(&g_AApA[slot][b], t2);
        }
    }
}

// ---------------- init: rhs = adj + lam*x ; x0=p=rhs ; twiddles; scalars ----
__global__ void k_init(const float2* __restrict__ x, const float2* __restrict__ adj, float2* __restrict__ xout){
    int idx = blockIdx.y*HWc + blockIdx.x*256 + threadIdx.x;
    float2 xv = x[idx], av = adj[idx];
    float2 rhs = make_float2(fmaf(LAMf, xv.x, av.x), fmaf(LAMf, xv.y, av.y));
    xout[idx] = rhs;
    g_p[idx]  = rhs;
    if (blockIdx.x == 0 && blockIdx.y == 0){
        if (threadIdx.x < Bn) g_rd0[threadIdx.x] = 0.f;
        if (threadIdx.x < 128){
            (&g_pApA[0][0])[threadIdx.x] = 0.f;
            (&g_rApA[0][0])[threadIdx.x] = 0.f;
            (&g_AApA[0][0])[threadIdx.x] = 0.f;
        }
        for (int j = threadIdx.x; j < 384; j += 256){
            double s, c;
            sincos(TWO_PI_D * (double)j / 384.0, &s, &c);
            g_T[j] = make_float2((float)c, (float)(-s));
        }
    }
}

// ---------------- cvt: maps fp32 -> fp16 ----------------
__global__ void k_cvt(const float2* __restrict__ maps){
    size_t i = (size_t)blockIdx.x*256 + threadIdx.x;
    float4 v = reinterpret_cast<const float4*>(maps)[i];
    h2x2 o;
    o.a = __floats2half2_rn(v.x, v.y);
    o.c = __floats2half2_rn(v.z, v.w);
    reinterpret_cast<h2x2*>(g_M)[i] = o;
}

// ---------------- mprep: permuted mask table (stored-order, *INVN) ---------
__global__ void k_mprep(const float* __restrict__ mask){
    const int p = blockIdx.x, b = blockIdx.y;
    const int t = threadIdx.x;
    const int kx = (p >> 5) + 12*(int)br5((unsigned)(p & 31));
    const int ky = (t >> 5) + 12*(int)br5((unsigned)(t & 31));
    g_MSK[((size_t)(b*Wn + p))*384 + t] =
        __ldg(mask + (size_t)b*HWc + (size_t)ky*Wn + kx) * INVN;
}

// ---------------- fin: x += alpha_last * p  (float4) ----------------
__global__ void k_fin(float2* __restrict__ x, int itTot){
    int b = blockIdx.y;
    float alpha, beta;
    cg_chain(itTot, b, alpha, beta);
    int i4 = blockIdx.x*256 + threadIdx.x;
    int idx = b*(HWc/2) + i4;
    const float4* p4 = reinterpret_cast<const float4*>(g_p);
    float4* x4 = reinterpret_cast<float4*>(x);
    float4 pv = p4[idx], xv = x4[idx];
    x4[idx] = make_float4(fmaf(alpha,pv.x,xv.x), fmaf(alpha,pv.y,xv.y),
                          fmaf(alpha,pv.z,xv.z), fmaf(alpha,pv.w,xv.w));
}

// ---------------- launch ----------------
extern "C" void kernel_launch(void* const* d_in, const int* in_sizes, int n_in,
                              void* d_out, int out_size){
    const float2* x    = (const float2*)d_in[0];
    const float2* adj  = (const float2*)d_in[1];
    const float2* maps = (const float2*)d_in[2];
    const float*  mask = (const float*)d_in[3];
    float2* xout = (float2*)d_out;

    dim3 gElem(HWc/256, Bn);   // k_init
    dim3 gVec(HWc/512, Bn);    // k_fin
    dim3 gRow(Hn/4, Bn);       // 96 x 8, 128 thr
    dim3 gCol(Wn/8, Cn, Bn);   // 48 x 12 x 8, 256 thr
    dim3 gMsk(Wn, Bn);         // 384 x 8, 384 thr
    const int gCvt = (int)(((size_t)Bn*Cn*HWc) / 512);

    k_init<<<gElem, 256>>>(x, adj, xout);
    k_cvt<<<gCvt, 256>>>(maps);
    k_mprep<<<gMsk, 384>>>(mask);

    // init Aop: r = rhs - Aop(rhs); p = r; rd0 = <r,r>
    k_fwd<false><<<gRow, 128>>>(xout, 0);
    k_col<<<gCol, 256>>>();
    k_inv<true><<<gRow, 128>>>(0);

    for (int it = 0; it < 10; ++it){
        if (it) k_fwd<true><<<gRow, 128>>>(xout, it);
        else    k_fwd<false><<<gRow, 128>>>(xout, 0);
        k_col<<<gCol, 256>>>();
        k_inv<false><<<gRow, 128>>>(it);
    }
    k_fin<<<gVec, 256>>>(xout, 10);
}

// round 16
// speedup vs baseline: 1.0506x; 1.0506x over previous
#include <cuda_runtime.h>
#include <cuda_fp16.h>

#define Bn 8
#define Cn 12
#define Hn 384
#define Wn 384
#define HWc (Hn*Wn)
#define BHWc (Bn*HWc)
#define LAMf 0.05f
#define EPSf 1e-12f
#define INVN (1.0f/147456.0f)
#define SQ3H 0.86602540378443864676f
#define TWO_PI_D 6.283185307179586476925286766559

// ---------------- scratch (static device arrays; allowed) ----------------
__device__ __half2 g_Y[(size_t)Bn*Cn*HWc]; // coil k-space, fp16, 56.6 MB
__device__ __half2 g_M[(size_t)Bn*Cn*HWc]; // maps, fp16, 28.3 MB
__device__ float  g_MSK[(size_t)Bn*Wn*384]; // permuted mask*INVN, 4.7 MB
__device__ float2 g_p[BHWc];
__device__ float2 g_r[BHWc];
__device__ float2 g_Ap[BHWc];
__device__ float  g_rd0[Bn];                // <r0,r0>
__device__ float  g_pApA[16][Bn];           // per-iteration <p,Ap>
__device__ float  g_rApA[16][Bn];           // per-iteration <r,Ap>
__device__ float  g_AApA[16][Bn];           // per-iteration <Ap,Ap>
__device__ float2 g_T[384];                 // W_384^j = (cos, -sin)

struct h2x2 { __half2 a, c; };

// ---------------- complex helpers ----------------
__device__ __forceinline__ float2 cmul(float2 a, float2 b){
    return make_float2(fmaf(a.x,b.x,-a.y*b.y), fmaf(a.x,b.y, a.y*b.x));
}
__device__ __forceinline__ float2 cadd(float2 a, float2 b){ return make_float2(a.x+b.x, a.y+b.y); }
__device__ __forceinline__ float2 csub(float2 a, float2 b){ return make_float2(a.x-b.x, a.y-b.y); }
__device__ __forceinline__ unsigned br5(unsigned x){ return __brev(x) >> 27; }
__device__ __forceinline__ __half2 c2h(float2 v){ return __floats2half2_rn(v.x, v.y); }
__device__ __forceinline__ float2 h2c(__half2 h){ return __half22float2(h); }

// scalar CG chain: after the loop, alpha = alpha_{it-1}, beta = beta_{it-1}
__device__ __forceinline__ void cg_chain(int it, int b, float& alpha, float& beta){
    float rd = g_rd0[b];
    alpha = 0.f; beta = 0.f;
    for (int k = 0; k < it; k++){
        float pap = g_pApA[k][b], rap = g_rApA[k][b], aap = g_AApA[k][b];
        alpha = rd / (pap + EPSf);
        float rdn = fmaf(alpha*alpha, aap, fmaf(-2.f*alpha, rap, rd));
        beta = rdn / (rd + EPSf);
        rd = rdn;
    }
}

// ---------------- FFT-12 in registers, natural in/out, unnormalized -------
template<bool INV>
__device__ __forceinline__ void fft12(float2* v){
    float2 F0[4], F1[4], F2[4];
    {
        float2 x0=v[0], x1=v[3], x2=v[6], x3=v[9];
        float2 t0=cadd(x0,x2), t1=csub(x0,x2), t2=cadd(x1,x3), t3=csub(x1,x3);
        F0[0]=cadd(t0,t2); F0[2]=csub(t0,t2);
        if(!INV){ F0[1]=make_float2(t1.x+t3.y, t1.y-t3.x); F0[3]=make_float2(t1.x-t3.y, t1.y+t3.x); }
        else    { F0[1]=make_float2(t1.x-t3.y, t1.y+t3.x); F0[3]=make_float2(t1.x+t3.y, t1.y-t3.x); }
    }
    {
        float2 x0=v[1], x1=v[4], x2=v[7], x3=v[10];
        float2 t0=cadd(x0,x2), t1=csub(x0,x2), t2=cadd(x1,x3), t3=csub(x1,x3);
        F1[0]=cadd(t0,t2); F1[2]=csub(t0,t2);
        if(!INV){ F1[1]=make_float2(t1.x+t3.y, t1.y-t3.x); F1[3]=make_float2(t1.x-t3.y, t1.y+t3.x); }
        else    { F1[1]=make_float2(t1.x-t3.y, t1.y+t3.x); F1[3]=make_float2(t1.x+t3.y, t1.y-t3.x); }
    }
    {
        float2 x0=v[2], x1=v[5], x2=v[8], x3=v[11];
        float2 t0=cadd(x0,x2), t1=csub(x0,x2), t2=cadd(x1,x3), t3=csub(x1,x3);
        F2[0]=cadd(t0,t2); F2[2]=csub(t0,t2);
        if(!INV){ F2[1]=make_float2(t1.x+t3.y, t1.y-t3.x); F2[3]=make_float2(t1.x-t3.y, t1.y+t3.x); }
        else    { F2[1]=make_float2(t1.x-t3.y, t1.y+t3.x); F2[3]=make_float2(t1.x+t3.y, t1.y-t3.x); }
    }
    const float c1 = SQ3H, s1 = 0.5f;
    const float sg = INV ? -1.f : 1.f;
    F1[1] = cmul(F1[1], make_float2(c1, -sg*s1));
    F2[1] = cmul(F2[1], make_float2(s1, -sg*c1));
    F1[2] = cmul(F1[2], make_float2(s1, -sg*c1));
    F2[2] = cmul(F2[2], make_float2(-s1, -sg*c1));
    F1[3] = INV ? make_float2(-F1[3].y, F1[3].x) : make_float2(F1[3].y, -F1[3].x);
    F2[3] = make_float2(-F2[3].x, -F2[3].y);
    #pragma unroll
    for (int k4 = 0; k4 < 4; k4++){
        float2 a=F0[k4], b=F1[k4], c=F2[k4];
        float2 s=cadd(b,c), d=csub(b,c);
        v[k4] = cadd(a, s);
        float ex = a.x - 0.5f*s.x, ey = a.y - 0.5f*s.y;
        if(!INV){
            v[k4+4] = make_float2(ex + SQ3H*d.y, ey - SQ3H*d.x);
            v[k4+8] = make_float2(ex - SQ3H*d.y, ey + SQ3H*d.x);
        } else {
            v[k4+4] = make_float2(ex - SQ3H*d.y, ey + SQ3H*d.x);
            v[k4+8] = make_float2(ex + SQ3H*d.y, ey - SQ3H*d.x);
        }
    }
}

// ---------------- FFT-32 across lanes ----------------
__device__ __forceinline__ void fft32_fwd(float2* v, const float2* tw, unsigned lane){
    #pragma unroll
    for (int s = 0; s < 5; s++){
        const int h = 16 >> s;
        const bool up = (lane & h) != 0;
        #pragma unroll
        for (int j = 0; j < 12; j++){
            float2 t;
            t.x = __shfl_xor_sync(0xffffffffu, v[j].x, h);
            t.y = __shfl_xor_sync(0xffffffffu, v[j].y, h);
            float2 nv = up ? csub(t, v[j]) : cadd(v[j], t);
            if (s < 4 && up) nv = cmul(nv, tw[s]);
            v[j] = nv;
        }
    }
}
__device__ __forceinline__ void fft32_inv(float2* v, const float2* twc, unsigned lane){
    #pragma unroll
    for (int s = 0; s < 5; s++){
        const int h = 1 << s;
        const bool up = (lane & h) != 0;
        #pragma unroll
        for (int j = 0; j < 12; j++){
            float2 vv = v[j];
            if (s > 0 && up) vv = cmul(vv, twc[4 - s]);
            float2 t;
            t.x = __shfl_xor_sync(0xffffffffu, vv.x, h);
            t.y = __shfl_xor_sync(0xffffffffu, vv.y, h);
            v[j] = up ? csub(t, vv) : cadd(vv, t);
        }
    }
}

__device__ __forceinline__ void load_tw32_fwd(unsigned lane, float2* tw){
    tw[0] = __ldg(&g_T[(lane & 15) * 12]);
    tw[1] = __ldg(&g_T[((lane & 7) * 2) * 12]);
    tw[2] = __ldg(&g_T[((lane & 3) * 4) * 12]);
    tw[3] = __ldg(&g_T[((lane & 1) * 8) * 12]);
}
__device__ __forceinline__ void load_tw32_inv(unsigned lane, float2* tw){
    float2 a;
    a = __ldg(&g_T[(lane & 15) * 12]); tw[0] = make_float2(a.x, -a.y);
    a = __ldg(&g_T[((lane & 7) * 2) * 12]); tw[1] = make_float2(a.x, -a.y);
    a = __ldg(&g_T[((lane & 3) * 4) * 12]); tw[2] = make_float2(a.x, -a.y);
    a = __ldg(&g_T[((lane & 1) * 8) * 12]); tw[3] = make_float2(a.x, -a.y);
}

template<bool CONJ, int NT>
__device__ __forceinline__ void build_t12(float2* T, int tid){
    for (int i = tid; i < 384; i += NT){
        int j = i >> 5, l = i & 31;
        float2 w = __ldg(&g_T[l*j]);
        T[i] = CONJ ? make_float2(w.x, -w.y) : w;
    }
}

// ============================================================================
// K1: warp per (b,row): fwd row FFT of m_c*p for all 12 coils.
// V staged in smem; update phase float4-vectorized; occ 6 (R14 winner).
// UPD: fused CG update — x += a*p; r -= a*Ap; p = r + b*p.
// ============================================================================
template<bool UPD>
__global__ void __launch_bounds__(128,6) k_fwd(float2* __restrict__ x, int it){
    __shared__ float2 Tf[384];
    __shared__ float2 Vs[4*384];
    const unsigned lane = threadIdx.x & 31;
    const int wid = threadIdx.x >> 5;
    const int row = blockIdx.x*4 + wid;
    const int b   = blockIdx.y;
    const int vb  = wid*384;

    build_t12<false,128>(Tf, threadIdx.x);
    float2 tw32[4];
    load_tw32_fwd(lane, tw32);

    const int gbase = (b*Hn + row)*Wn;     // even -> float4-aligned
    float4* vs4 = reinterpret_cast<float4*>(Vs + vb);
    if (UPD){
        float alpha, beta;
        cg_chain(it, b, alpha, beta);
        const float4* r4c  = reinterpret_cast<const float4*>(g_r  + gbase);
        const float4* p4c  = reinterpret_cast<const float4*>(g_p  + gbase);
        const float4* ap4c = reinterpret_cast<const float4*>(g_Ap + gbase);
        float4* x4  = reinterpret_cast<float4*>(x    + gbase);
        float4* r4  = reinterpret_cast<float4*>(g_r  + gbase);
        float4* p4  = reinterpret_cast<float4*>(g_p  + gbase);
        #pragma unroll
        for (int g = 0; g < 6; g++){
            int e = lane + 32*g;           // float4 index (2 complex)
            float4 rv = r4c[e], pv = p4c[e], ap = ap4c[e], xv = x4[e];
            x4[e] = make_float4(fmaf(alpha,pv.x,xv.x), fmaf(alpha,pv.y,xv.y),
                                fmaf(alpha,pv.z,xv.z), fmaf(alpha,pv.w,xv.w));
            rv = make_float4(fmaf(-alpha,ap.x,rv.x), fmaf(-alpha,ap.y,rv.y),
                             fmaf(-alpha,ap.z,rv.z), fmaf(-alpha,ap.w,rv.w));
            r4[e] = rv;
            float4 pn = make_float4(fmaf(beta,pv.x,rv.x), fmaf(beta,pv.y,rv.y),
                                    fmaf(beta,pv.z,rv.z), fmaf(beta,pv.w,rv.w));
            p4[e] = pn;
            vs4[e] = pn;
        }
    } else {
        const float4* p4c = reinterpret_cast<const float4*>(g_p + gbase);
        #pragma unroll
        for (int g = 0; g < 6; g++){
            int e = lane + 32*g;
            vs4[e] = p4c[e];
        }
    }
    __syncthreads();

    for (int c = 0; c < Cn; c++){
        const __half2* mp = g_M + ((size_t)(b*Cn + c)*Hn + row)*Wn;
        float2 X[12];
        #pragma unroll
        for (int j = 0; j < 12; j++)
            X[j] = cmul(h2c(__ldg(mp + lane + 32*j)), Vs[vb + lane + 32*j]);
        fft12<false>(X);
        #pragma unroll
        for (int j = 1; j < 12; j++) X[j] = cmul(X[j], Tf[j*32 + lane]);
        fft32_fwd(X, tw32, lane);
        __half2* yo = g_Y + ((size_t)(b*Cn + c)*Hn + row)*Wn;
        #pragma unroll
        for (int j = 0; j < 12; j++) yo[lane + 32*j] = c2h(X[j]);
    }
}

// ============================================================================
// K2: block = 8 columns of one (b,c): col FFT -> mask*INVN -> col IFFT.
// Single merged twiddle-table build.
// ============================================================================
__global__ void __launch_bounds__(256,3) k_col(){
    __shared__ __half2 S[384*9];
    __shared__ float2 Tf[384], Ti[384];
    const unsigned lane = threadIdx.x & 31;
    const int wcol = threadIdx.x >> 5;
    const int tid = threadIdx.x;
    const int p0 = blockIdx.x*8, c = blockIdx.y, b = blockIdx.z;
    const size_t base = (size_t)(b*Cn + c)*HWc;

    for (int i = tid; i < 384; i += 256){
        int j = i >> 5, l = i & 31;
        float2 w = __ldg(&g_T[l*j]);
        Tf[i] = w;
        Ti[i] = make_float2(w.x, -w.y);
    }
    float2 tw32[4], tw32c[4];
    load_tw32_fwd(lane, tw32);
    #pragma unroll
    for (int s = 0; s < 4; s++) tw32c[s] = make_float2(tw32[s].x, -tw32[s].y);

    const int p = p0 + wcol;
    const float* mp2 = g_MSK + ((size_t)(b*Wn + p))*384;
    float msk[12];
    #pragma unroll
    for (int j = 0; j < 12; j++) msk[j] = __ldg(mp2 + lane + 32*j);

    #pragma unroll
    for (int k = 0; k < 3; k++){
        int idx = tid + k*256;
        int h = idx >> 1, c0 = (idx & 1)*4;
        uint4 v = *reinterpret_cast<const uint4*>(g_Y + base + (size_t)h*Wn + p0 + c0);
        unsigned* sp = reinterpret_cast<unsigned*>(S) + h*9 + c0;
        sp[0] = v.x; sp[1] = v.y; sp[2] = v.z; sp[3] = v.w;
    }
    __syncthreads();

    float2 X[12];
    #pragma unroll
    for (int j = 0; j < 12; j++) X[j] = h2c(S[(lane + 32*j)*9 + wcol]);

    fft12<false>(X);
    #pragma unroll
    for (int j = 1; j < 12; j++) X[j] = cmul(X[j], Tf[j*32 + lane]);
    fft32_fwd(X, tw32, lane);

    #pragma unroll
    for (int j = 0; j < 12; j++) X[j] = make_float2(X[j].x*msk[j], X[j].y*msk[j]);

    fft32_inv(X, tw32c, lane);
    #pragma unroll
    for (int j = 1; j < 12; j++) X[j] = cmul(X[j], Ti[j*32 + lane]);
    fft12<true>(X);

    #pragma unroll
    for (int j = 0; j < 12; j++) S[(lane + 32*j)*9 + wcol] = c2h(X[j]);
    __syncthreads();

    #pragma unroll
    for (int k = 0; k < 3; k++){
        int idx = tid + k*256;
        int h = idx >> 1, c0 = (idx & 1)*4;
        const unsigned* sp = reinterpret_cast<const unsigned*>(S) + h*9 + c0;
        uint4 v = make_uint4(sp[0], sp[1], sp[2], sp[3]);
        *reinterpret_cast<uint4*>(g_Y + base + (size_t)h*Wn + p0 + c0) = v;
    }
}

// ============================================================================
// K3: warp per (b,row): inv row FFT per coil, acc (in smem) += conj(m)*z.
// Epilogue float4-vectorized; occ 6 (R14 winner).
// INIT: r = rhs - (acc + lam*p); p = r; reduce <r,r> -> g_rd0.
// else: Ap = acc + lam*p; reduce <p,Ap>, <r,Ap>, <Ap,Ap>.
// ============================================================================
template<bool INIT>
__global__ void __launch_bounds__(128,6) k_inv(int slot){
    __shared__ float2 Ti[384];
    __shared__ float2 Acc[4*384];
    __shared__ float red[4][3];
    const unsigned lane = threadIdx.x & 31;
    const int wid = threadIdx.x >> 5;
    const int row = blockIdx.x*4 + wid;
    const int b   = blockIdx.y;
    const int ab  = wid*384;

    build_t12<true,128>(Ti, threadIdx.x);
    float2 tw32c[4];
    load_tw32_inv(lane, tw32c);
    #pragma unroll
    for (int j = 0; j < 12; j++) Acc[ab + lane + 32*j] = make_float2(0.f, 0.f);
    __syncthreads();

    for (int c = 0; c < Cn; c++){
        const size_t cb = ((size_t)(b*Cn + c)*Hn + row)*Wn;
        float2 X[12];
        #pragma unroll
        for (int j = 0; j < 12; j++) X[j] = h2c(g_Y[cb + lane + 32*j]);
        fft32_inv(X, tw32c, lane);
        #pragma unroll
        for (int j = 1; j < 12; j++) X[j] = cmul(X[j], Ti[j*32 + lane]);
        fft12<true>(X);
        const __half2* mp = g_M + cb;
        #pragma unroll
        for (int j = 0; j < 12; j++){
            float2 m = h2c(__ldg(mp + lane + 32*j));
            float2 z = X[j];
            float2 a0 = Acc[ab + lane + 32*j];
            Acc[ab + lane + 32*j] = make_float2(
                fmaf(m.x, z.x, fmaf(m.y, z.y, a0.x)),
                fmaf(m.x, z.y, fmaf(-m.y, z.x, a0.y)));
        }
    }

    const int gbase = (b*Hn + row)*Wn;
    const float4* acc4 = reinterpret_cast<const float4*>(Acc + ab);
    const float4* p4c  = reinterpret_cast<const float4*>(g_p + gbase);
    float s0 = 0.f, s1 = 0.f, s2 = 0.f;
    #pragma unroll
    for (int g = 0; g < 6; g++){
        int e = lane + 32*g;               // float4 index (2 complex)
        float4 av = acc4[e];
        float4 pv = p4c[e];
        float4 o = make_float4(fmaf(LAMf,pv.x,av.x), fmaf(LAMf,pv.y,av.y),
                               fmaf(LAMf,pv.z,av.z), fmaf(LAMf,pv.w,av.w));
        if (INIT){
            float4 rv = make_float4(pv.x-o.x, pv.y-o.y, pv.z-o.z, pv.w-o.w);
            reinterpret_cast<float4*>(g_r + gbase)[e] = rv;
            reinterpret_cast<float4*>(g_p + gbase)[e] = rv;
            s0 = fmaf(rv.x,rv.x, fmaf(rv.y,rv.y, fmaf(rv.z,rv.z, fmaf(rv.w,rv.w, s0))));
        } else {
            float4 rv = reinterpret_cast<const float4*>(g_r + gbase)[e];
            reinterpret_cast<float4*>(g_Ap + gbase)[e] = o;
            s0 = fmaf(pv.x,o.x, fmaf(pv.y,o.y, fmaf(pv.z,o.z, fmaf(pv.w,o.w, s0))));
            s1 = fmaf(rv.x,o.x, fmaf(rv.y,o.y, fmaf(rv.z,o.z, fmaf(rv.w,o.w, s1))));
            s2 = fmaf(o.x,o.x, fmaf(o.y,o.y, fmaf(o.z,o.z, fmaf(o.w,o.w, s2))));
        }
    }
    #pragma unroll
    for (int off = 16; off > 0; off >>= 1){
        s0 += __shfl_down_sync(0xffffffffu, s0, off);
        if (!INIT){
            s1 += __shfl_down_sync(0xffffffffu, s1, off);
            s2 += __shfl_down_sync(0xffffffffu, s2, off);
        }
    }
    if (lane == 0){ red[wid][0] = s0; red[wid][1] = s1; red[wid][2] = s2; }
    __syncthreads();
    if (threadIdx.x == 0){
        float t0 = red[0][0]+red[1][0]+red[2][0]+red[3][0];
        if (INIT){
            atomicAdd(&g_rd0[b], t0);
        } else {
            float t1 = red[0][1]+red[1][1]+red[2][1]+red[3][1];
            float t2 = red[0][2]+red[1][2]+red[2][2]+red[3][2];
            atomicAdd(&g_pApA[slot][b], t0);
            atomicAdd(&g_rApA[slot][b], t1);
            atomicAdd(&g_AApA[slot][b], t2);
        }
    }
}

// ---------------- init: rhs = adj + lam*x ; x0=p=rhs ; twiddles; scalars ----
__global__ void k_init(const float2* __restrict__ x, const float2* __restrict__ adj, float2* __restrict__ xout){
    int idx = blockIdx.y*HWc + blockIdx.x*256 + threadIdx.x;
    float2 xv = x[idx], av = adj[idx];
    float2 rhs = make_float2(fmaf(LAMf, xv.x, av.x), fmaf(LAMf, xv.y, av.y));
    xout[idx] = rhs;
    g_p[idx]  = rhs;
    if (blockIdx.x == 0 && blockIdx.y == 0){
        if (threadIdx.x < Bn) g_rd0[threadIdx.x] = 0.f;
        if (threadIdx.x < 128){
            (&g_pApA[0][0])[threadIdx.x] = 0.f;
            (&g_rApA[0][0])[threadIdx.x] = 0.f;
            (&g_AApA[0][0])[threadIdx.x] = 0.f;
        }
        for (int j = threadIdx.x; j < 384; j += 256){
            double s, c;
            sincos(TWO_PI_D * (double)j / 384.0, &s, &c);
            g_T[j] = make_float2((float)c, (float)(-s));
        }
    }
}

// ---------------- cvt: maps fp32 -> fp16 ----------------
__global__ void k_cvt(const float2* __restrict__ maps){
    size_t i = (size_t)blockIdx.x*256 + threadIdx.x;
    float4 v = reinterpret_cast<const float4*>(maps)[i];
    h2x2 o;
    o.a = __floats2half2_rn(v.x, v.y);
    o.c = __floats2half2_rn(v.z, v.w);
    reinterpret_cast<h2x2*>(g_M)[i] = o;
}

// ---------------- mprep: permuted mask table (stored-order, *INVN) ---------
__global__ void k_mprep(const float* __restrict__ mask){
    const int p = blockIdx.x, b = blockIdx.y;
    const int t = threadIdx.x;
    const int kx = (p >> 5) + 12*(int)br5((unsigned)(p & 31));
    const int ky = (t >> 5) + 12*(int)br5((unsigned)(t & 31));
    g_MSK[((size_t)(b*Wn + p))*384 + t] =
        __ldg(mask + (size_t)b*HWc + (size_t)ky*Wn + kx) * INVN;
}

// ---------------- fin: x += alpha_last * p  (float4) ----------------
__global__ void k_fin(float2* __restrict__ x, int itTot){
    int b = blockIdx.y;
    float alpha, beta;
    cg_chain(itTot, b, alpha, beta);
    int i4 = blockIdx.x*256 + threadIdx.x;
    int idx = b*(HWc/2) + i4;
    const float4* p4 = reinterpret_cast<const float4*>(g_p);
    float4* x4 = reinterpret_cast<float4*>(x);
    float4 pv = p4[idx], xv = x4[idx];
    x4[idx] = make_float4(fmaf(alpha,pv.x,xv.x), fmaf(alpha,pv.y,xv.y),
                          fmaf(alpha,pv.z,xv.z), fmaf(alpha,pv.w,xv.w));
}

// ---------------- launch ----------------
extern "C" void kernel_launch(void* const* d_in, const int* in_sizes, int n_in,
                              void* d_out, int out_size){
    const float2* x    = (const float2*)d_in[0];
    const float2* adj  = (const float2*)d_in[1];
    const float2* maps = (const float2*)d_in[2];
    const float*  mask = (const float*)d_in[3];
    float2* xout = (float2*)d_out;

    dim3 gElem(HWc/256, Bn);   // k_init
    dim3 gVec(HWc/512, Bn);    // k_fin
    dim3 gRow(Hn/4, Bn);       // 96 x 8, 128 thr
    dim3 gCol(Wn/8, Cn, Bn);   // 48 x 12 x 8, 256 thr
    dim3 gMsk(Wn, Bn);         // 384 x 8, 384 thr
    const int gCvt = (int)(((size_t)Bn*Cn*HWc) / 512);

    k_init<<<gElem, 256>>>(x, adj, xout);
    k_cvt<<<gCvt, 256>>>(maps);
    k_mprep<<<gMsk, 384>>>(mask);

    // init Aop: r = rhs - Aop(rhs); p = r; rd0 = <r,r>
    k_fwd<false><<<gRow, 128>>>(xout, 0);
    k_col<<<gCol, 256>>>();
    k_inv<true><<<gRow, 128>>>(0);

    for (int it = 0; it < 10; ++it){
        if (it) k_fwd<true><<<gRow, 128>>>(xout, it);
        else    k_fwd<false><<<gRow, 128>>>(xout, 0);
        k_col<<<gCol, 256>>>();
        k_inv<false><<<gRow, 128>>>(it);
    }
    k_fin<<<gVec, 256>>>(xout, 10);
}